// round 12
// baseline (speedup 1.0000x reference)
#include <cuda_runtime.h>
#include <cuda_fp16.h>

#define NN 60000
#define EE 1200000
#define DD 64
#define OUTD 192   // K * D

// ---- device scratch ----
__device__ int    g_deg[NN];
__device__ int    g_rowptr[NN + 1];
__device__ int    g_cursor[NN];
__device__ int    g_col[EE];
__device__ float  g_dinv[NN];            // d^-1/2
__device__ __half g_Xs_h [NN * DD];      // fp16: X0 * d^-1/2   (gather src, pass 1)
__device__ __half g_X1s_h[NN * DD];      // fp16: X1 * d^-1/2   (gather src, pass 2)
__device__ float  g_X1  [NN * DD];       // fp32: raw X1 (for exact recurrence term)

// bit-reinterpret helpers (no-op in SASS)
__device__ __forceinline__ unsigned h2_bits(__half2 h) {
    return *(unsigned*)&h;
}
__device__ __forceinline__ float2 bits_f2(unsigned u) {
    __half2 h = *(__half2*)&u;
    return __half22float2(h);
}

__global__ void k_zero_deg() {
    int i = blockIdx.x * blockDim.x + threadIdx.x;
    if (i < NN) g_deg[i] = 0;
}

__global__ void k_deg(const int* __restrict__ dst) {
    int t = blockIdx.x * blockDim.x + threadIdx.x;
    if (t < EE / 4) {
        int4 d = ((const int4*)dst)[t];
        atomicAdd(&g_deg[d.x], 1);
        atomicAdd(&g_deg[d.y], 1);
        atomicAdd(&g_deg[d.z], 1);
        atomicAdd(&g_deg[d.w], 1);
    }
}

// Single-block chunked scan, int4-vectorized. chunk=60 (4-aligned, 1000*60=NN).
__global__ void k_scan() {
    const int T = 1024;
    const int CH = 60;
    int tid = threadIdx.x;
    int start = tid * CH;
    int sum = 0;
    if (start < NN) {
        const int4* p = (const int4*)(g_deg + start);
        #pragma unroll
        for (int i = 0; i < CH / 4; i++) {
            int4 v = p[i];
            sum += v.x + v.y + v.z + v.w;
        }
    }
    __shared__ int sh[T];
    sh[tid] = sum;
    __syncthreads();
    for (int off = 1; off < T; off <<= 1) {
        int v = (tid >= off) ? sh[tid - off] : 0;
        __syncthreads();
        sh[tid] += v;
        __syncthreads();
    }
    int run = sh[tid] - sum;   // exclusive prefix of this chunk
    if (start < NN) {
        const int4* p = (const int4*)(g_deg + start);
        int4* rp = (int4*)(g_rowptr + start);
        int4* cp = (int4*)(g_cursor + start);
        #pragma unroll
        for (int i = 0; i < CH / 4; i++) {
            int4 d = p[i];
            int4 r;
            r.x = run;
            r.y = r.x + d.x;
            r.z = r.y + d.y;
            r.w = r.z + d.z;
            run = r.w + d.w;
            rp[i] = r;
            cp[i] = r;
        }
    }
    if (tid == T - 1) g_rowptr[NN] = run;
}

// 16 threads per node, 1 float4 each: dinv, Xs_h = fp16(feat*dinv), out[:,0:64]=relu(feat)
__global__ void k_prep(const float* __restrict__ feat, float* __restrict__ out) {
    int t = blockIdx.x * blockDim.x + threadIdx.x;
    if (t >= NN * 16) return;
    int i = t >> 4;
    int c = (t & 15) << 2;
    float dinv = rsqrtf(fmaxf((float)g_deg[i], 1.0f));
    if ((t & 15) == 0) g_dinv[i] = dinv;
    float4 f = *(const float4*)(feat + (size_t)i * DD + c);
    __half2 h0 = __float22half2_rn(make_float2(f.x * dinv, f.y * dinv));
    __half2 h1 = __float22half2_rn(make_float2(f.z * dinv, f.w * dinv));
    uint2 packed = make_uint2(h2_bits(h0), h2_bits(h1));
    *(uint2*)((char*)g_Xs_h + (size_t)i * DD * 2 + c * 2) = packed;
    *(float4*)(out + (size_t)i * OUTD + c) =
        make_float4(fmaxf(f.x, 0.f), fmaxf(f.y, 0.f), fmaxf(f.z, 0.f), fmaxf(f.w, 0.f));
}

__global__ void k_fill(const int* __restrict__ src, const int* __restrict__ dst) {
    int t = blockIdx.x * blockDim.x + threadIdx.x;
    if (t < EE / 4) {
        int4 s = ((const int4*)src)[t];
        int4 d = ((const int4*)dst)[t];
        int p0 = atomicAdd(&g_cursor[d.x], 1); g_col[p0] = s.x;
        int p1 = atomicAdd(&g_cursor[d.y], 1); g_col[p1] = s.y;
        int p2 = atomicAdd(&g_cursor[d.z], 1); g_col[p2] = s.z;
        int p3 = atomicAdd(&g_cursor[d.w], 1); g_col[p3] = s.w;
    }
}

// Warp gathers fp16 rows (128B each) for node w.
// Half-warps handle alternating edges; lane fl in [0,16) loads 4 halfs (8B).
// Result: lanes 0-15 hold fp32 sums for features [4*fl, 4*fl+4).
__device__ __forceinline__ float4 gather_sum_h(const __half* __restrict__ table,
                                               int beg, int end, int lane) {
    int half_id = lane >> 4;
    int fl = lane & 15;
    float ax = 0.f, ay = 0.f, az = 0.f, aw = 0.f;
    const char* base = (const char*)table;
    int e = beg + half_id;
    for (; e + 6 < end; e += 8) {
        int s0 = g_col[e];
        int s1 = g_col[e + 2];
        int s2 = g_col[e + 4];
        int s3 = g_col[e + 6];
        uint2 p0 = *(const uint2*)(base + (size_t)s0 * 128 + fl * 8);
        uint2 p1 = *(const uint2*)(base + (size_t)s1 * 128 + fl * 8);
        uint2 p2 = *(const uint2*)(base + (size_t)s2 * 128 + fl * 8);
        uint2 p3 = *(const uint2*)(base + (size_t)s3 * 128 + fl * 8);
        #pragma unroll
        for (int j = 0; j < 4; j++) {
            uint2 p = (j == 0) ? p0 : (j == 1) ? p1 : (j == 2) ? p2 : p3;
            float2 lo = bits_f2(p.x);
            float2 hi = bits_f2(p.y);
            ax += lo.x; ay += lo.y; az += hi.x; aw += hi.y;
        }
    }
    for (; e + 2 < end; e += 4) {
        int s0 = g_col[e];
        int s1 = g_col[e + 2];
        uint2 p0 = *(const uint2*)(base + (size_t)s0 * 128 + fl * 8);
        uint2 p1 = *(const uint2*)(base + (size_t)s1 * 128 + fl * 8);
        float2 l0 = bits_f2(p0.x), h0 = bits_f2(p0.y);
        float2 l1 = bits_f2(p1.x), h1 = bits_f2(p1.y);
        ax += l0.x + l1.x; ay += l0.y + l1.y;
        az += h0.x + h1.x; aw += h0.y + h1.y;
    }
    for (; e < end; e += 2) {
        int s = g_col[e];
        uint2 p = *(const uint2*)(base + (size_t)s * 128 + fl * 8);
        float2 lo = bits_f2(p.x);
        float2 hi = bits_f2(p.y);
        ax += lo.x; ay += lo.y; az += hi.x; aw += hi.y;
    }
    ax += __shfl_xor_sync(0xFFFFFFFF, ax, 16);
    ay += __shfl_xor_sync(0xFFFFFFFF, ay, 16);
    az += __shfl_xor_sync(0xFFFFFFFF, az, 16);
    aw += __shfl_xor_sync(0xFFFFFFFF, aw, 16);
    return make_float4(ax, ay, az, aw);
}

// pass 1: h = dinv * sum(Xs[col]); X1 = -rn*h + (rn-1)*X0
// writes g_X1 (fp32), g_X1s_h (fp16 scaled), out[:, 64:128] = relu(X1)
__global__ void k_spmm1(const float* __restrict__ feat,
                        const float* __restrict__ lambda_max,
                        float* __restrict__ out) {
    int w = (blockIdx.x * blockDim.x + threadIdx.x) >> 5;
    int lane = threadIdx.x & 31;
    if (w >= NN) return;
    int beg = g_rowptr[w];
    int end = g_rowptr[w + 1];
    float4 acc = gather_sum_h(g_Xs_h, beg, end, lane);
    if (lane < 16) {
        float dinv = g_dinv[w];
        float rn = 2.0f / lambda_max[0];
        float a = -rn * dinv;
        float b = rn - 1.0f;
        float4 x0 = *(const float4*)(feat + (size_t)w * DD + lane * 4);
        float4 x1;
        x1.x = a * acc.x + b * x0.x;
        x1.y = a * acc.y + b * x0.y;
        x1.z = a * acc.z + b * x0.z;
        x1.w = a * acc.w + b * x0.w;
        *(float4*)(g_X1 + (size_t)w * DD + lane * 4) = x1;
        __half2 h0 = __float22half2_rn(make_float2(x1.x * dinv, x1.y * dinv));
        __half2 h1 = __float22half2_rn(make_float2(x1.z * dinv, x1.w * dinv));
        uint2 packed = make_uint2(h2_bits(h0), h2_bits(h1));
        *(uint2*)((char*)g_X1s_h + (size_t)w * 128 + lane * 8) = packed;
        *(float4*)(out + (size_t)w * OUTD + DD + lane * 4) =
            make_float4(fmaxf(x1.x, 0.f), fmaxf(x1.y, 0.f),
                        fmaxf(x1.z, 0.f), fmaxf(x1.w, 0.f));
    }
}

// pass 2: h2 = dinv * sum(X1s[col]); X2 = -2*rn*h2 + 2*(rn-1)*X1 - X0
// writes out[:, 128:192] = relu(X2). X1 term uses the exact fp32 buffer.
__global__ void k_spmm2(const float* __restrict__ feat,
                        const float* __restrict__ lambda_max,
                        float* __restrict__ out) {
    int w = (blockIdx.x * blockDim.x + threadIdx.x) >> 5;
    int lane = threadIdx.x & 31;
    if (w >= NN) return;
    int beg = g_rowptr[w];
    int end = g_rowptr[w + 1];
    float4 acc = gather_sum_h(g_X1s_h, beg, end, lane);
    if (lane < 16) {
        float dinv = g_dinv[w];
        float rn = 2.0f / lambda_max[0];
        float a = -2.0f * rn * dinv;
        float b = 2.0f * (rn - 1.0f);
        float4 x0 = *(const float4*)(feat + (size_t)w * DD + lane * 4);
        float4 x1 = *(const float4*)(g_X1 + (size_t)w * DD + lane * 4);
        float4 x2;
        x2.x = a * acc.x + b * x1.x - x0.x;
        x2.y = a * acc.y + b * x1.y - x0.y;
        x2.z = a * acc.z + b * x1.z - x0.z;
        x2.w = a * acc.w + b * x1.w - x0.w;
        *(float4*)(out + (size_t)w * OUTD + 2 * DD + lane * 4) =
            make_float4(fmaxf(x2.x, 0.f), fmaxf(x2.y, 0.f),
                        fmaxf(x2.z, 0.f), fmaxf(x2.w, 0.f));
    }
}

extern "C" void kernel_launch(void* const* d_in, const int* in_sizes, int n_in,
                              void* d_out, int out_size) {
    const float* feat       = (const float*)d_in[0];
    const int*   src        = (const int*)d_in[1];
    const int*   dst        = (const int*)d_in[2];
    const float* lambda_max = (const float*)d_in[3];
    float* out = (float*)d_out;

    // Side stream + events for forking k_prep off the CSR-build chain.
    // Created once; host-side objects only (no device allocations).
    static cudaStream_t s_prep = nullptr;
    static cudaEvent_t ev_deg = nullptr, ev_prep = nullptr;
    if (s_prep == nullptr) {
        cudaStreamCreateWithFlags(&s_prep, cudaStreamNonBlocking);
        cudaEventCreateWithFlags(&ev_deg, cudaEventDisableTiming);
        cudaEventCreateWithFlags(&ev_prep, cudaEventDisableTiming);
    }

    const int TB = 256;
    k_zero_deg<<<(NN + TB - 1) / TB, TB>>>();
    k_deg<<<(EE / 4 + TB - 1) / TB, TB>>>(dst);
    cudaEventRecord(ev_deg, 0);

    // fork: prep depends only on g_deg, runs concurrently with scan+fill
    cudaStreamWaitEvent(s_prep, ev_deg, 0);
    k_prep<<<(NN * 16 + TB - 1) / TB, TB, 0, s_prep>>>(feat, out);
    cudaEventRecord(ev_prep, s_prep);

    k_scan<<<1, 1024>>>();
    k_fill<<<(EE / 4 + TB - 1) / TB, TB>>>(src, dst);

    // join: spmm1 needs both the CSR (main stream) and Xs_h (side stream)
    cudaStreamWaitEvent(0, ev_prep, 0);
    k_spmm1<<<(NN * 32 + TB - 1) / TB, TB>>>(feat, lambda_max, out);
    k_spmm2<<<(NN * 32 + TB - 1) / TB, TB>>>(feat, lambda_max, out);
}

// round 13
// speedup vs baseline: 1.7890x; 1.7890x over previous
#include <cuda_runtime.h>
#include <cuda_fp16.h>

#define NN 60000
#define EE 1200000
#define DD 64
#define OUTD 192   // K * D

// ---- device scratch ----
__device__ int    g_deg[NN];
__device__ int    g_rowptr[NN + 1];
__device__ int    g_cursor[NN];
__device__ int    g_col[EE];
__device__ int    g_blocksum[60];
__device__ int    g_blockoff[61];
__device__ float  g_dinv[NN];            // d^-1/2
__device__ __half g_Xs_h [NN * DD];      // fp16: X0 * d^-1/2   (gather src, pass 1)
__device__ __half g_X1s_h[NN * DD];      // fp16: X1 * d^-1/2   (gather src, pass 2)
__device__ float  g_X1  [NN * DD];       // fp32: raw X1 (for exact recurrence term)

// bit-reinterpret helpers (no-op in SASS)
__device__ __forceinline__ unsigned h2_bits(__half2 h) {
    return *(unsigned*)&h;
}
__device__ __forceinline__ float2 bits_f2(unsigned u) {
    __half2 h = *(__half2*)&u;
    return __half22float2(h);
}

__global__ void k_zero_deg() {
    int i = blockIdx.x * blockDim.x + threadIdx.x;
    if (i < NN) g_deg[i] = 0;
}

__global__ void k_deg(const int* __restrict__ dst) {
    int t = blockIdx.x * blockDim.x + threadIdx.x;
    if (t < EE / 4) {
        int4 d = ((const int4*)dst)[t];
        atomicAdd(&g_deg[d.x], 1);
        atomicAdd(&g_deg[d.y], 1);
        atomicAdd(&g_deg[d.z], 1);
        atomicAdd(&g_deg[d.w], 1);
    }
}

// ---- hierarchical scan: 60 blocks x 1000 elems, all phases grid-parallel ----
__global__ void k_scan_a() {
    __shared__ int sh[1024];
    int b = blockIdx.x;
    int t = threadIdx.x;
    int i = b * 1000 + t;
    int v = (t < 1000) ? g_deg[i] : 0;
    sh[t] = v;
    __syncthreads();
    #pragma unroll
    for (int off = 1; off < 1024; off <<= 1) {
        int x = (t >= off) ? sh[t - off] : 0;
        __syncthreads();
        sh[t] += x;
        __syncthreads();
    }
    if (t < 1000) g_rowptr[i] = sh[t] - v;   // local exclusive prefix
    if (t == 999) g_blocksum[b] = sh[t];     // block total (inclusive of elem 999)
}

__global__ void k_scan_b() {
    __shared__ int sh[64];
    int t = threadIdx.x;
    int v = (t < 60) ? g_blocksum[t] : 0;
    sh[t] = v;
    __syncthreads();
    #pragma unroll
    for (int off = 1; off < 64; off <<= 1) {
        int x = (t >= off) ? sh[t - off] : 0;
        __syncthreads();
        sh[t] += x;
        __syncthreads();
    }
    if (t < 60) g_blockoff[t] = sh[t] - v;   // exclusive
    if (t == 63) g_blockoff[60] = sh[63];    // grand total
}

__global__ void k_scan_c() {
    int b = blockIdx.x;
    int t = threadIdx.x;
    int off = g_blockoff[b];
    int i = b * 1000 + t;
    if (t < 1000) {
        int r = g_rowptr[i] + off;
        g_rowptr[i] = r;
        g_cursor[i] = r;
    }
    if (b == 0 && t == 0) g_rowptr[NN] = g_blockoff[60];
}

// 16 threads per node, 1 float4 each: dinv, Xs_h = fp16(feat*dinv), out[:,0:64]=relu(feat)
__global__ void k_prep(const float* __restrict__ feat, float* __restrict__ out) {
    int t = blockIdx.x * blockDim.x + threadIdx.x;
    if (t >= NN * 16) return;
    int i = t >> 4;
    int c = (t & 15) << 2;
    float dinv = rsqrtf(fmaxf((float)g_deg[i], 1.0f));
    if ((t & 15) == 0) g_dinv[i] = dinv;
    float4 f = *(const float4*)(feat + (size_t)i * DD + c);
    __half2 h0 = __float22half2_rn(make_float2(f.x * dinv, f.y * dinv));
    __half2 h1 = __float22half2_rn(make_float2(f.z * dinv, f.w * dinv));
    uint2 packed = make_uint2(h2_bits(h0), h2_bits(h1));
    *(uint2*)((char*)g_Xs_h + (size_t)i * DD * 2 + c * 2) = packed;
    *(float4*)(out + (size_t)i * OUTD + c) =
        make_float4(fmaxf(f.x, 0.f), fmaxf(f.y, 0.f), fmaxf(f.z, 0.f), fmaxf(f.w, 0.f));
}

__global__ void k_fill(const int* __restrict__ src, const int* __restrict__ dst) {
    int t = blockIdx.x * blockDim.x + threadIdx.x;
    if (t < EE / 4) {
        int4 s = ((const int4*)src)[t];
        int4 d = ((const int4*)dst)[t];
        int p0 = atomicAdd(&g_cursor[d.x], 1); g_col[p0] = s.x;
        int p1 = atomicAdd(&g_cursor[d.y], 1); g_col[p1] = s.y;
        int p2 = atomicAdd(&g_cursor[d.z], 1); g_col[p2] = s.z;
        int p3 = atomicAdd(&g_cursor[d.w], 1); g_col[p3] = s.w;
    }
}

// Warp gathers fp16 rows (128B each) for node w.
// Half-warps handle alternating edges; lane fl in [0,16) loads 4 halfs (8B).
// Result: lanes 0-15 hold fp32 sums for features [4*fl, 4*fl+4).
__device__ __forceinline__ float4 gather_sum_h(const __half* __restrict__ table,
                                               int beg, int end, int lane) {
    int half_id = lane >> 4;
    int fl = lane & 15;
    float ax = 0.f, ay = 0.f, az = 0.f, aw = 0.f;
    const char* base = (const char*)table;
    int e = beg + half_id;
    for (; e + 6 < end; e += 8) {
        int s0 = g_col[e];
        int s1 = g_col[e + 2];
        int s2 = g_col[e + 4];
        int s3 = g_col[e + 6];
        uint2 p0 = *(const uint2*)(base + (size_t)s0 * 128 + fl * 8);
        uint2 p1 = *(const uint2*)(base + (size_t)s1 * 128 + fl * 8);
        uint2 p2 = *(const uint2*)(base + (size_t)s2 * 128 + fl * 8);
        uint2 p3 = *(const uint2*)(base + (size_t)s3 * 128 + fl * 8);
        #pragma unroll
        for (int j = 0; j < 4; j++) {
            uint2 p = (j == 0) ? p0 : (j == 1) ? p1 : (j == 2) ? p2 : p3;
            float2 lo = bits_f2(p.x);
            float2 hi = bits_f2(p.y);
            ax += lo.x; ay += lo.y; az += hi.x; aw += hi.y;
        }
    }
    for (; e + 2 < end; e += 4) {
        int s0 = g_col[e];
        int s1 = g_col[e + 2];
        uint2 p0 = *(const uint2*)(base + (size_t)s0 * 128 + fl * 8);
        uint2 p1 = *(const uint2*)(base + (size_t)s1 * 128 + fl * 8);
        float2 l0 = bits_f2(p0.x), h0 = bits_f2(p0.y);
        float2 l1 = bits_f2(p1.x), h1 = bits_f2(p1.y);
        ax += l0.x + l1.x; ay += l0.y + l1.y;
        az += h0.x + h1.x; aw += h0.y + h1.y;
    }
    for (; e < end; e += 2) {
        int s = g_col[e];
        uint2 p = *(const uint2*)(base + (size_t)s * 128 + fl * 8);
        float2 lo = bits_f2(p.x);
        float2 hi = bits_f2(p.y);
        ax += lo.x; ay += lo.y; az += hi.x; aw += hi.y;
    }
    ax += __shfl_xor_sync(0xFFFFFFFF, ax, 16);
    ay += __shfl_xor_sync(0xFFFFFFFF, ay, 16);
    az += __shfl_xor_sync(0xFFFFFFFF, az, 16);
    aw += __shfl_xor_sync(0xFFFFFFFF, aw, 16);
    return make_float4(ax, ay, az, aw);
}

// pass 1: h = dinv * sum(Xs[col]); X1 = -rn*h + (rn-1)*X0
// writes g_X1 (fp32), g_X1s_h (fp16 scaled), out[:, 64:128] = relu(X1)
__global__ void k_spmm1(const float* __restrict__ feat,
                        const float* __restrict__ lambda_max,
                        float* __restrict__ out) {
    int w = (blockIdx.x * blockDim.x + threadIdx.x) >> 5;
    int lane = threadIdx.x & 31;
    if (w >= NN) return;
    int beg = g_rowptr[w];
    int end = g_rowptr[w + 1];
    float4 acc = gather_sum_h(g_Xs_h, beg, end, lane);
    if (lane < 16) {
        float dinv = g_dinv[w];
        float rn = 2.0f / lambda_max[0];
        float a = -rn * dinv;
        float b = rn - 1.0f;
        float4 x0 = *(const float4*)(feat + (size_t)w * DD + lane * 4);
        float4 x1;
        x1.x = a * acc.x + b * x0.x;
        x1.y = a * acc.y + b * x0.y;
        x1.z = a * acc.z + b * x0.z;
        x1.w = a * acc.w + b * x0.w;
        *(float4*)(g_X1 + (size_t)w * DD + lane * 4) = x1;
        __half2 h0 = __float22half2_rn(make_float2(x1.x * dinv, x1.y * dinv));
        __half2 h1 = __float22half2_rn(make_float2(x1.z * dinv, x1.w * dinv));
        uint2 packed = make_uint2(h2_bits(h0), h2_bits(h1));
        *(uint2*)((char*)g_X1s_h + (size_t)w * 128 + lane * 8) = packed;
        *(float4*)(out + (size_t)w * OUTD + DD + lane * 4) =
            make_float4(fmaxf(x1.x, 0.f), fmaxf(x1.y, 0.f),
                        fmaxf(x1.z, 0.f), fmaxf(x1.w, 0.f));
    }
}

// pass 2: h2 = dinv * sum(X1s[col]); X2 = -2*rn*h2 + 2*(rn-1)*X1 - X0
// writes out[:, 128:192] = relu(X2). X1 term uses the exact fp32 buffer.
__global__ void k_spmm2(const float* __restrict__ feat,
                        const float* __restrict__ lambda_max,
                        float* __restrict__ out) {
    int w = (blockIdx.x * blockDim.x + threadIdx.x) >> 5;
    int lane = threadIdx.x & 31;
    if (w >= NN) return;
    int beg = g_rowptr[w];
    int end = g_rowptr[w + 1];
    float4 acc = gather_sum_h(g_X1s_h, beg, end, lane);
    if (lane < 16) {
        float dinv = g_dinv[w];
        float rn = 2.0f / lambda_max[0];
        float a = -2.0f * rn * dinv;
        float b = 2.0f * (rn - 1.0f);
        float4 x0 = *(const float4*)(feat + (size_t)w * DD + lane * 4);
        float4 x1 = *(const float4*)(g_X1 + (size_t)w * DD + lane * 4);
        float4 x2;
        x2.x = a * acc.x + b * x1.x - x0.x;
        x2.y = a * acc.y + b * x1.y - x0.y;
        x2.z = a * acc.z + b * x1.z - x0.z;
        x2.w = a * acc.w + b * x1.w - x0.w;
        *(float4*)(out + (size_t)w * OUTD + 2 * DD + lane * 4) =
            make_float4(fmaxf(x2.x, 0.f), fmaxf(x2.y, 0.f),
                        fmaxf(x2.z, 0.f), fmaxf(x2.w, 0.f));
    }
}

extern "C" void kernel_launch(void* const* d_in, const int* in_sizes, int n_in,
                              void* d_out, int out_size) {
    const float* feat       = (const float*)d_in[0];
    const int*   src        = (const int*)d_in[1];
    const int*   dst        = (const int*)d_in[2];
    const float* lambda_max = (const float*)d_in[3];
    float* out = (float*)d_out;

    const int TB = 256;
    k_zero_deg<<<(NN + TB - 1) / TB, TB>>>();
    k_deg<<<(EE / 4 + TB - 1) / TB, TB>>>(dst);
    k_scan_a<<<60, 1024>>>();
    k_scan_b<<<1, 64>>>();
    k_scan_c<<<60, 1024>>>();
    k_prep<<<(NN * 16 + TB - 1) / TB, TB>>>(feat, out);
    k_fill<<<(EE / 4 + TB - 1) / TB, TB>>>(src, dst);
    k_spmm1<<<(NN * 32 + TB - 1) / TB, TB>>>(feat, lambda_max, out);
    k_spmm2<<<(NN * 32 + TB - 1) / TB, TB>>>(feat, lambda_max, out);
}

// round 15
// speedup vs baseline: 1.8368x; 1.0267x over previous
#include <cuda_runtime.h>
#include <cuda_fp16.h>

#define NN 60000
#define EE 1200000
#define DD 64
#define OUTD 192   // K * D
#define FILL_B 1172   // ceil((EE/4)/256)
#define PREP_B 3750   // (NN*16)/256

// ---- device scratch ----
__device__ int    g_deg[NN];        // zero at load; re-zeroed by k_spmm2 each run
__device__ int    g_rowptr[NN + 1];
__device__ int    g_cursor[NN];
__device__ int    g_col[EE];
__device__ int    g_blocksum[60];
__device__ float  g_dinv[NN];            // d^-1/2
__device__ __half g_Xs_h [NN * DD];      // fp16: X0 * d^-1/2   (gather src, pass 1)
__device__ __half g_X1s_h[NN * DD];      // fp16: X1 * d^-1/2   (gather src, pass 2)
__device__ float  g_X1  [NN * DD];       // fp32: raw X1 (for exact recurrence term)

// bit-reinterpret helpers (no-op in SASS)
__device__ __forceinline__ unsigned h2_bits(__half2 h) {
    return *(unsigned*)&h;
}
__device__ __forceinline__ float2 bits_f2(unsigned u) {
    __half2 h = *(__half2*)&u;
    return __half22float2(h);
}

__global__ void k_deg(const int* __restrict__ dst) {
    int t = blockIdx.x * blockDim.x + threadIdx.x;
    if (t < EE / 4) {
        int4 d = ((const int4*)dst)[t];
        atomicAdd(&g_deg[d.x], 1);
        atomicAdd(&g_deg[d.y], 1);
        atomicAdd(&g_deg[d.z], 1);
        atomicAdd(&g_deg[d.w], 1);
    }
}

// ---- hierarchical scan: 60 blocks x 1000 elems ----
__global__ void k_scan_a() {
    __shared__ int sh[1024];
    int b = blockIdx.x;
    int t = threadIdx.x;
    int i = b * 1000 + t;
    int v = (t < 1000) ? g_deg[i] : 0;
    sh[t] = v;
    __syncthreads();
    #pragma unroll
    for (int off = 1; off < 1024; off <<= 1) {
        int x = (t >= off) ? sh[t - off] : 0;
        __syncthreads();
        sh[t] += x;
        __syncthreads();
    }
    if (t < 1000) g_rowptr[i] = sh[t] - v;   // local exclusive prefix
    if (t == 999) g_blocksum[b] = sh[t];     // block total
}

// apply phase: every block redundantly scans the 60 block sums (cheap), then
// adds its offset and writes rowptr/cursor. Replaces the old k_scan_b kernel.
__global__ void k_scan_c() {
    __shared__ int sh[64];
    int b = blockIdx.x;
    int t = threadIdx.x;
    if (t < 64) sh[t] = (t < 60) ? g_blocksum[t] : 0;
    __syncthreads();
    #pragma unroll
    for (int off = 1; off < 64; off <<= 1) {
        int x = (t >= off && t < 64) ? sh[t - off] : 0;
        __syncthreads();
        if (t < 64) sh[t] += x;
        __syncthreads();
    }
    int boff = (b == 0) ? 0 : sh[b - 1];   // exclusive offset for this block
    int i = b * 1000 + t;
    if (t < 1000) {
        int r = g_rowptr[i] + boff;
        g_rowptr[i] = r;
        g_cursor[i] = r;
    }
    if (b == 0 && t == 0) g_rowptr[NN] = sh[59];
}

// Fused CSR-fill + prep. Blocks [0, FILL_B) scatter edges into g_col;
// blocks [FILL_B, FILL_B+PREP_B) compute dinv, fp16 table, and out[:,0:64].
// The two halves touch disjoint data and overlap atomic latency with BW.
__global__ void k_fillprep(const int* __restrict__ src, const int* __restrict__ dst,
                           const float* __restrict__ feat, float* __restrict__ out) {
    if (blockIdx.x < FILL_B) {
        int t = blockIdx.x * blockDim.x + threadIdx.x;
        if (t < EE / 4) {
            int4 s = ((const int4*)src)[t];
            int4 d = ((const int4*)dst)[t];
            int p0 = atomicAdd(&g_cursor[d.x], 1); g_col[p0] = s.x;
            int p1 = atomicAdd(&g_cursor[d.y], 1); g_col[p1] = s.y;
            int p2 = atomicAdd(&g_cursor[d.z], 1); g_col[p2] = s.z;
            int p3 = atomicAdd(&g_cursor[d.w], 1); g_col[p3] = s.w;
        }
    } else {
        int t = (blockIdx.x - FILL_B) * blockDim.x + threadIdx.x;
        if (t >= NN * 16) return;
        int i = t >> 4;
        int c = (t & 15) << 2;
        float dinv = rsqrtf(fmaxf((float)g_deg[i], 1.0f));
        if ((t & 15) == 0) g_dinv[i] = dinv;
        float4 f = *(const float4*)(feat + (size_t)i * DD + c);
        __half2 h0 = __float22half2_rn(make_float2(f.x * dinv, f.y * dinv));
        __half2 h1 = __float22half2_rn(make_float2(f.z * dinv, f.w * dinv));
        uint2 packed = make_uint2(h2_bits(h0), h2_bits(h1));
        *(uint2*)((char*)g_Xs_h + (size_t)i * DD * 2 + c * 2) = packed;
        *(float4*)(out + (size_t)i * OUTD + c) =
            make_float4(fmaxf(f.x, 0.f), fmaxf(f.y, 0.f), fmaxf(f.z, 0.f), fmaxf(f.w, 0.f));
    }
}

// Warp gathers fp16 rows (128B each) for node w.
// Half-warps handle alternating edges; lane fl in [0,16) loads 4 halfs (8B).
// Result: lanes 0-15 hold fp32 sums for features [4*fl, 4*fl+4).
__device__ __forceinline__ float4 gather_sum_h(const __half* __restrict__ table,
                                               int beg, int end, int lane) {
    int half_id = lane >> 4;
    int fl = lane & 15;
    float ax = 0.f, ay = 0.f, az = 0.f, aw = 0.f;
    const char* base = (const char*)table;
    int e = beg + half_id;
    for (; e + 6 < end; e += 8) {
        int s0 = g_col[e];
        int s1 = g_col[e + 2];
        int s2 = g_col[e + 4];
        int s3 = g_col[e + 6];
        uint2 p0 = *(const uint2*)(base + (size_t)s0 * 128 + fl * 8);
        uint2 p1 = *(const uint2*)(base + (size_t)s1 * 128 + fl * 8);
        uint2 p2 = *(const uint2*)(base + (size_t)s2 * 128 + fl * 8);
        uint2 p3 = *(const uint2*)(base + (size_t)s3 * 128 + fl * 8);
        #pragma unroll
        for (int j = 0; j < 4; j++) {
            uint2 p = (j == 0) ? p0 : (j == 1) ? p1 : (j == 2) ? p2 : p3;
            float2 lo = bits_f2(p.x);
            float2 hi = bits_f2(p.y);
            ax += lo.x; ay += lo.y; az += hi.x; aw += hi.y;
        }
    }
    for (; e + 2 < end; e += 4) {
        int s0 = g_col[e];
        int s1 = g_col[e + 2];
        uint2 p0 = *(const uint2*)(base + (size_t)s0 * 128 + fl * 8);
        uint2 p1 = *(const uint2*)(base + (size_t)s1 * 128 + fl * 8);
        float2 l0 = bits_f2(p0.x), h0 = bits_f2(p0.y);
        float2 l1 = bits_f2(p1.x), h1 = bits_f2(p1.y);
        ax += l0.x + l1.x; ay += l0.y + l1.y;
        az += h0.x + h1.x; aw += h0.y + h1.y;
    }
    for (; e < end; e += 2) {
        int s = g_col[e];
        uint2 p = *(const uint2*)(base + (size_t)s * 128 + fl * 8);
        float2 lo = bits_f2(p.x);
        float2 hi = bits_f2(p.y);
        ax += lo.x; ay += lo.y; az += hi.x; aw += hi.y;
    }
    ax += __shfl_xor_sync(0xFFFFFFFF, ax, 16);
    ay += __shfl_xor_sync(0xFFFFFFFF, ay, 16);
    az += __shfl_xor_sync(0xFFFFFFFF, az, 16);
    aw += __shfl_xor_sync(0xFFFFFFFF, aw, 16);
    return make_float4(ax, ay, az, aw);
}

// pass 1: h = dinv * sum(Xs[col]); X1 = -rn*h + (rn-1)*X0
// writes g_X1 (fp32), g_X1s_h (fp16 scaled), out[:, 64:128] = relu(X1)
__global__ void k_spmm1(const float* __restrict__ feat,
                        const float* __restrict__ lambda_max,
                        float* __restrict__ out) {
    int w = (blockIdx.x * blockDim.x + threadIdx.x) >> 5;
    int lane = threadIdx.x & 31;
    if (w >= NN) return;
    int beg = g_rowptr[w];
    int end = g_rowptr[w + 1];
    float4 acc = gather_sum_h(g_Xs_h, beg, end, lane);
    if (lane < 16) {
        float dinv = g_dinv[w];
        float rn = 2.0f / lambda_max[0];
        float a = -rn * dinv;
        float b = rn - 1.0f;
        float4 x0 = *(const float4*)(feat + (size_t)w * DD + lane * 4);
        float4 x1;
        x1.x = a * acc.x + b * x0.x;
        x1.y = a * acc.y + b * x0.y;
        x1.z = a * acc.z + b * x0.z;
        x1.w = a * acc.w + b * x0.w;
        *(float4*)(g_X1 + (size_t)w * DD + lane * 4) = x1;
        __half2 h0 = __float22half2_rn(make_float2(x1.x * dinv, x1.y * dinv));
        __half2 h1 = __float22half2_rn(make_float2(x1.z * dinv, x1.w * dinv));
        uint2 packed = make_uint2(h2_bits(h0), h2_bits(h1));
        *(uint2*)((char*)g_X1s_h + (size_t)w * 128 + lane * 8) = packed;
        *(float4*)(out + (size_t)w * OUTD + DD + lane * 4) =
            make_float4(fmaxf(x1.x, 0.f), fmaxf(x1.y, 0.f),
                        fmaxf(x1.z, 0.f), fmaxf(x1.w, 0.f));
    }
}

// pass 2: h2 = dinv * sum(X1s[col]); X2 = -2*rn*h2 + 2*(rn-1)*X1 - X0
// writes out[:, 128:192] = relu(X2). Also re-zeros g_deg for the next replay.
__global__ void k_spmm2(const float* __restrict__ feat,
                        const float* __restrict__ lambda_max,
                        float* __restrict__ out) {
    int w = (blockIdx.x * blockDim.x + threadIdx.x) >> 5;
    int lane = threadIdx.x & 31;
    if (w >= NN) return;
    int beg = g_rowptr[w];
    int end = g_rowptr[w + 1];
    float4 acc = gather_sum_h(g_X1s_h, beg, end, lane);
    if (lane == 31) g_deg[w] = 0;   // reset for next launch (graph replay)
    if (lane < 16) {
        float dinv = g_dinv[w];
        float rn = 2.0f / lambda_max[0];
        float a = -2.0f * rn * dinv;
        float b = 2.0f * (rn - 1.0f);
        float4 x0 = *(const float4*)(feat + (size_t)w * DD + lane * 4);
        float4 x1 = *(const float4*)(g_X1 + (size_t)w * DD + lane * 4);
        float4 x2;
        x2.x = a * acc.x + b * x1.x - x0.x;
        x2.y = a * acc.y + b * x1.y - x0.y;
        x2.z = a * acc.z + b * x1.z - x0.z;
        x2.w = a * acc.w + b * x1.w - x0.w;
        *(float4*)(out + (size_t)w * OUTD + 2 * DD + lane * 4) =
            make_float4(fmaxf(x2.x, 0.f), fmaxf(x2.y, 0.f),
                        fmaxf(x2.z, 0.f), fmaxf(x2.w, 0.f));
    }
}

extern "C" void kernel_launch(void* const* d_in, const int* in_sizes, int n_in,
                              void* d_out, int out_size) {
    const float* feat       = (const float*)d_in[0];
    const int*   src        = (const int*)d_in[1];
    const int*   dst        = (const int*)d_in[2];
    const float* lambda_max = (const float*)d_in[3];
    float* out = (float*)d_out;

    const int TB = 256;
    k_deg<<<(EE / 4 + TB - 1) / TB, TB>>>(dst);
    k_scan_a<<<60, 1024>>>();
    k_scan_c<<<60, 1024>>>();
    k_fillprep<<<FILL_B + PREP_B, TB>>>(src, dst, feat, out);
    k_spmm1<<<(NN * 32 + TB - 1) / TB, TB>>>(feat, lambda_max, out);
    k_spmm2<<<(NN * 32 + TB - 1) / TB, TB>>>(feat, lambda_max, out);
}